// round 12
// baseline (speedup 1.0000x reference)
#include <cuda_runtime.h>

#define NUMLAB 670000
#define Bn 128
#define Cn 65536
#define Mn 16
#define Hn 512
#define Kn 200
#define KMn 3200        // Kn*Mn
#define SBn 16          // scan segments per row
#define SEGCAP 256      // survivor capacity per segment (expected ~18)
#define ROWCAP 2048     // survivor capacity per row
#define THRESH 2.62f    // raw-logit collect threshold (~288 survivors/row)

// ---- scratch (no allocations allowed) ----
__device__ int      g_scnt[Bn * SBn];
__device__ unsigned g_su[Bn * SBn * SEGCAP];
__device__ int      g_si[Bn * SBn * SEGCAP];
__device__ int      g_cands[Bn * KMn];
__device__ float    g_cscores[Bn * KMn];

// monotone float->uint key: descending float == descending key
__device__ __forceinline__ unsigned fkey(float x) {
    unsigned u = __float_as_uint(x);
    return (u & 0x80000000u) ? ~u : (u | 0x80000000u);
}
__device__ __forceinline__ float unfkey(unsigned k) {
    return __uint_as_float((k & 0x80000000u) ? (k ^ 0x80000000u) : ~k);
}

// ============================================================
// Kernel 1: full-chip streaming collect. grid (SBn, Bn), 256thr.
// Survivors staged in smem, dumped coalesced to a private
// per-segment slot. No global atomics.
// ============================================================
__global__ void __launch_bounds__(256) collect_kernel(const float* __restrict__ logits) {
    const int row = blockIdx.y;
    const int seg = blockIdx.x;
    const int n4  = Cn / 4 / SBn;                 // 1024 float4 per block
    const float4* rp4 = (const float4*)(logits + (size_t)row * Cn) + seg * n4;
    const int base = seg * n4 * 4;
    const int tid = threadIdx.x;

    __shared__ unsigned s_u[SEGCAP];
    __shared__ int      s_i[SEGCAP];
    __shared__ int      s_cnt;
    if (tid == 0) s_cnt = 0;
    __syncthreads();

    float4 a0 = rp4[tid];
    float4 a1 = rp4[tid + 256];
    float4 a2 = rp4[tid + 512];
    float4 a3 = rp4[tid + 768];

    float vals[16] = {a0.x,a0.y,a0.z,a0.w, a1.x,a1.y,a1.z,a1.w,
                      a2.x,a2.y,a2.z,a2.w, a3.x,a3.y,a3.z,a3.w};
    #pragma unroll
    for (int t = 0; t < 16; t++) {
        if (vals[t] > THRESH) {
            int p = atomicAdd(&s_cnt, 1);
            if (p < SEGCAP) {
                s_u[p] = fkey(vals[t]);
                s_i[p] = base + (t >> 2) * 1024 + tid * 4 + (t & 3);
            }
        }
    }
    __syncthreads();
    const int c  = s_cnt;
    const int cc = min(c, SEGCAP);
    const size_t off = (size_t)(row * SBn + seg) * SEGCAP;
    if (tid < cc) {
        g_su[off + tid] = s_u[tid];
        g_si[off + tid] = s_i[tid];
    }
    if (tid == 0) g_scnt[row * SBn + seg] = c;
}

// ============================================================
// Kernel 2: per-row exact top-200 rank-select over survivors
// (value desc, index-asc ties) + cluster expansion + stable
// pad-compaction. One block (1024 thr) per row.
// Fast identity path when the row has no padding entries.
// Fallback (block-uniform trigger): exact 4x8-bit radix re-scan.
// ============================================================
__global__ void __launch_bounds__(1024) select_expand_kernel(const float* __restrict__ logits,
                                                             const int* __restrict__ clusters,
                                                             float* __restrict__ out) {
    const int row = blockIdx.x;
    const int tid = threadIdx.x;
    const int lane = tid & 31;
    const int wid  = tid >> 5;
    const float*  rp  = logits + (size_t)row * Cn;
    const float4* rp4 = (const float4*)rp;

    __shared__ unsigned s_bu[ROWCAP];      // 8 KB
    __shared__ int      s_bi[ROWCAP];      // 8 KB
    __shared__ int      s_segcnt[SBn];
    __shared__ int      s_segoff[SBn + 1];
    __shared__ int      s_tidx[Kn];
    __shared__ unsigned s_tku[Kn];
    __shared__ float    s_tsc[Kn];
    __shared__ int      s_wsum[32];
    __shared__ int      s_total;
    __shared__ unsigned s_red[256];
    __shared__ unsigned s_prefix;
    __shared__ int      s_kneed;
    __shared__ int      s_cnt;
    __shared__ int      s_bad;

    if (tid < SBn) s_segcnt[tid] = g_scnt[row * SBn + tid];
    __syncthreads();
    if (tid == 0) {
        int acc = 0, bad = 0;
        #pragma unroll
        for (int s = 0; s < SBn; s++) {
            s_segoff[s] = acc;
            int c = s_segcnt[s];
            if (c > SEGCAP) bad = 1;
            acc += min(c, SEGCAP);
        }
        s_segoff[SBn] = acc;
        if (acc < Kn || acc > ROWCAP) bad = 1;
        s_bad = bad;
    }
    __syncthreads();

    int m;
    if (!s_bad) {
        m = s_segoff[SBn];
        // coalesced gather: 64 threads per segment
        {
            const int s  = tid >> 6;            // 0..15
            const int lt = tid & 63;
            const int cnt = s_segoff[s + 1] - s_segoff[s];
            const size_t off = (size_t)(row * SBn + s) * SEGCAP;
            for (int i = lt; i < cnt; i += 64) {
                s_bu[s_segoff[s] + i] = g_su[off + i];
                s_bi[s_segoff[s] + i] = g_si[off + i];
            }
        }
        __syncthreads();
    } else {
        // ---- fallback: exact radix select of the Kn-th largest key ----
        if (tid == 0) { s_prefix = 0u; s_kneed = Kn; s_cnt = 0; }
        __syncthreads();
        for (int shift = 24; shift >= 0; shift -= 8) {
            if (tid < 256) s_red[tid] = 0u;
            __syncthreads();
            const unsigned pref = s_prefix;
            const unsigned mhi  = (shift == 24) ? 0u : (0xFFFFFFFFu << (shift + 8));
            for (int i = tid; i < Cn / 4; i += 1024) {
                float4 v = rp4[i];
                float vals[4] = {v.x, v.y, v.z, v.w};
                #pragma unroll
                for (int t = 0; t < 4; t++) {
                    unsigned u = fkey(vals[t]);
                    if ((u & mhi) == pref) atomicAdd(&s_red[(u >> shift) & 255], 1u);
                }
            }
            __syncthreads();
            if (tid == 0) {
                int kneed = s_kneed;
                int cum = 0;
                int b = 255;
                for (; b > 0; b--) {
                    int c = (int)s_red[b];
                    if (cum + c >= kneed) break;
                    cum += c;
                }
                s_kneed  = kneed - cum;
                s_prefix = pref | ((unsigned)b << shift);
            }
            __syncthreads();
        }
        const unsigned T = s_prefix;
        for (int i = tid; i < Cn / 4; i += 1024) {
            float4 v = rp4[i];
            float vals[4] = {v.x, v.y, v.z, v.w};
            #pragma unroll
            for (int t = 0; t < 4; t++) {
                unsigned u = fkey(vals[t]);
                if (u >= T) {
                    int p = atomicAdd(&s_cnt, 1);
                    if (p < ROWCAP) { s_bu[p] = u; s_bi[p] = i * 4 + t; }
                }
            }
        }
        __syncthreads();
        m = min(s_cnt, ROWCAP);
    }

    // ---- warp-cooperative exact rank-select, 4x-unrolled inner ----
    // rank(i) = #{j : u_j > u_i or (u_j == u_i and idx_j < idx_i)}
    for (int i = wid; i < m; i += 32) {
        const unsigned ui = s_bu[i];
        const int xi = s_bi[i];
        int r = 0;
        int j = lane;
        for (; j + 96 < m; j += 128) {
            unsigned u0 = s_bu[j], u1 = s_bu[j + 32], u2 = s_bu[j + 64], u3 = s_bu[j + 96];
            int b0 = s_bi[j], b1 = s_bi[j + 32], b2 = s_bi[j + 64], b3 = s_bi[j + 96];
            r += (u0 > ui || (u0 == ui && b0 < xi));
            r += (u1 > ui || (u1 == ui && b1 < xi));
            r += (u2 > ui || (u2 == ui && b2 < xi));
            r += (u3 > ui || (u3 == ui && b3 < xi));
        }
        for (; j < m; j += 32) {
            unsigned uj = s_bu[j];
            r += (uj > ui || (uj == ui && s_bi[j] < xi));
        }
        #pragma unroll
        for (int off = 16; off; off >>= 1)
            r += __shfl_xor_sync(0xffffffffu, r, off);
        if (lane == 0 && r < Kn) {
            s_tidx[r] = xi;
            s_tku[r]  = ui;
        }
    }
    __syncthreads();

    // parallel sigmoid over the 200 winners (key-inverse, no gmem read)
    if (tid < Kn) {
        float v = unfkey(s_tku[tid]);
        s_tsc[tid] = __fdividef(1.f, 1.f + __expf(-v));
    }
    __syncthreads();

    // ---- expand clusters ----
    int cand[4];
    float sc = 0.f;
    const int base = tid * 4;
    int haspad = 0;
    if (base < KMn) {
        const int j = base >> 4;                 // 4 | 16 => same topk slot for all 4
        const int idx = min(max(s_tidx[j], 0), Cn - 1);
        sc = s_tsc[j];
        const int4 cc = *(const int4*)(clusters + (size_t)idx * Mn + (base & 15));
        cand[0] = cc.x; cand[1] = cc.y; cand[2] = cc.z; cand[3] = cc.w;
        haspad = (cc.x == NUMLAB) | (cc.y == NUMLAB) | (cc.z == NUMLAB) | (cc.w == NUMLAB);
    }

    if (!__syncthreads_or(haspad)) {
        // ---- FAST PATH: no pads -> identity placement, vector stores ----
        if (base < KMn) {
            int4  ci = make_int4(cand[0], cand[1], cand[2], cand[3]);
            float4 cs = make_float4(sc, sc, sc, sc);
            float4 cf = make_float4((float)cand[0], (float)cand[1],
                                    (float)cand[2], (float)cand[3]);
            *(int4*)  (g_cands   + row * KMn + base) = ci;
            *(float4*)(g_cscores + row * KMn + base) = cs;
            *(float4*)(out + (size_t)row * KMn + base) = cf;
        }
        return;
    }

    // ---- SLOW PATH: stable pad-compaction via block scan ----
    int valid[4];
    int nv = 0;
    if (base < KMn) {
        #pragma unroll
        for (int t = 0; t < 4; t++) {
            valid[t] = (cand[t] != NUMLAB);
            nv += valid[t];
        }
    }
    int x = nv;
    #pragma unroll
    for (int off = 1; off < 32; off <<= 1) {
        int y = __shfl_up_sync(0xffffffffu, x, off);
        if (lane >= off) x += y;
    }
    if (lane == 31) s_wsum[wid] = x;
    __syncthreads();
    if (tid < 32) {
        int v = s_wsum[tid];
        int inc = v;
        #pragma unroll
        for (int off = 1; off < 32; off <<= 1) {
            int y = __shfl_up_sync(0xffffffffu, inc, off);
            if (tid >= off) inc += y;
        }
        s_wsum[tid] = inc - v;
        if (tid == 31) s_total = inc;
    }
    __syncthreads();
    const int total = s_total;
    int vb = s_wsum[wid] + x - nv;

    if (base < KMn) {
        #pragma unroll
        for (int t = 0; t < 4; t++) {
            int pos;
            if (valid[t]) { pos = vb; vb++; }
            else          { pos = total + (base + t) - vb; }
            g_cands[row * KMn + pos]   = cand[t];
            g_cscores[row * KMn + pos] = valid[t] ? sc : 0.f;
            out[(size_t)row * KMn + pos] = (float)cand[t];
        }
    }
}

// ============================================================
// Kernel 3: gather embeddings + dot with h_c, sigmoid, outputs.
// Warp per 4 candidates processed CONCURRENTLY: 4 labels loaded
// up front, 16 independent LDG.128 in flight (4x the in-flight
// bytes of the serial version), reductions deferred to the end.
// Per-accumulator FP order identical to before.
// ============================================================
__global__ void __launch_bounds__(256) score_kernel(const float* __restrict__ h_c,
                                                    const float* __restrict__ table,
                                                    float* __restrict__ out) {
    const int row = blockIdx.y;
    __shared__ float sh[Hn];
    for (int i = threadIdx.x; i < Hn; i += 256) sh[i] = h_c[(size_t)row * Hn + i];
    __syncthreads();

    const int warp = threadIdx.x >> 5;
    const int lane = threadIdx.x & 31;
    const int c0 = blockIdx.x * 32 + warp * 4;
    const float4* hv = (const float4*)sh;

    // 4 independent label loads
    const float4* er[4];
    #pragma unroll
    for (int t = 0; t < 4; t++) {
        int label = g_cands[row * KMn + c0 + t];
        label = min(max(label, 0), NUMLAB);
        er[t] = (const float4*)(table + (size_t)label * Hn);
    }

    float acc[4] = {0.f, 0.f, 0.f, 0.f};
    #pragma unroll
    for (int i = 0; i < 4; i++) {
        float4 h = hv[lane + i * 32];
        #pragma unroll
        for (int t = 0; t < 4; t++) {
            float4 e = er[t][lane + i * 32];
            acc[t] += e.x * h.x;
            acc[t] += e.y * h.y;
            acc[t] += e.z * h.z;
            acc[t] += e.w * h.w;
        }
    }

    #pragma unroll
    for (int t = 0; t < 4; t++) {
        #pragma unroll
        for (int off = 16; off; off >>= 1)
            acc[t] += __shfl_xor_sync(0xffffffffu, acc[t], off);
    }
    if (lane == 0) {
        #pragma unroll
        for (int t = 0; t < 4; t++) {
            const int c = c0 + t;
            float a = acc[t];
            float s = (a == 0.f) ? 0.f : (1.f / (1.f + __expf(-a)));
            out[(size_t)Bn * KMn     + (size_t)row * KMn + c] = s;
            out[(size_t)Bn * KMn * 2 + (size_t)row * KMn + c] = s * g_cscores[row * KMn + c];
        }
    }
}

extern "C" void kernel_launch(void* const* d_in, const int* in_sizes, int n_in,
                              void* d_out, int out_size) {
    // Bind inputs by element count (robust to metadata ordering):
    //   meta_logits  128*65536   = 8388608   f32
    //   h_c          128*512     = 65536     f32
    //   embed_table  670001*512  = 343040512 f32
    //   label_clusters 65536*16  = 1048576   i32 (jax x64 disabled -> int32)
    const float* meta = nullptr;
    const float* hc = nullptr;
    const float* table = nullptr;
    const int* clusters = nullptr;
    for (int i = 0; i < n_in; i++) {
        switch (in_sizes[i]) {
            case 8388608:   meta     = (const float*)d_in[i]; break;
            case 65536:     hc       = (const float*)d_in[i]; break;
            case 343040512: table    = (const float*)d_in[i]; break;
            case 1048576:   clusters = (const int*)d_in[i];   break;
            default: break;
        }
    }
    float* out = (float*)d_out; // 3 * 128 * 3200 f32: [cands | cand_scores | product]

    dim3 g1(SBn, Bn);
    collect_kernel<<<g1, 256>>>(meta);
    select_expand_kernel<<<Bn, 1024>>>(meta, clusters, out);
    dim3 g3(KMn / 32, Bn);
    score_kernel<<<g3, 256>>>(hc, table, out);
}

// round 13
// speedup vs baseline: 1.0182x; 1.0182x over previous
#include <cuda_runtime.h>

#define NUMLAB 670000
#define Bn 128
#define Cn 65536
#define Mn 16
#define Hn 512
#define Kn 200
#define KMn 3200        // Kn*Mn
#define SBn 16          // scan segments per row
#define SEGCAP 256      // survivor capacity per segment (expected ~18)
#define ROWCAP 2048     // survivor capacity per row
#define THRESH 2.62f    // raw-logit collect threshold (~288 survivors/row)

// ---- scratch (no allocations allowed) ----
__device__ int      g_scnt[Bn * SBn];
__device__ unsigned g_su[Bn * SBn * SEGCAP];
__device__ int      g_si[Bn * SBn * SEGCAP];
__device__ int      g_cands[Bn * KMn];
__device__ float    g_cscores[Bn * KMn];

// monotone float->uint key: descending float == descending key
__device__ __forceinline__ unsigned fkey(float x) {
    unsigned u = __float_as_uint(x);
    return (u & 0x80000000u) ? ~u : (u | 0x80000000u);
}
__device__ __forceinline__ float unfkey(unsigned k) {
    return __uint_as_float((k & 0x80000000u) ? (k ^ 0x80000000u) : ~k);
}

// ============================================================
// Kernel 1: full-chip streaming collect. grid (SBn, Bn), 256thr.
// Survivors staged in smem, dumped coalesced to a private
// per-segment slot. No global atomics.
// ============================================================
__global__ void __launch_bounds__(256) collect_kernel(const float* __restrict__ logits) {
    const int row = blockIdx.y;
    const int seg = blockIdx.x;
    const int n4  = Cn / 4 / SBn;                 // 1024 float4 per block
    const float4* rp4 = (const float4*)(logits + (size_t)row * Cn) + seg * n4;
    const int base = seg * n4 * 4;
    const int tid = threadIdx.x;

    __shared__ unsigned s_u[SEGCAP];
    __shared__ int      s_i[SEGCAP];
    __shared__ int      s_cnt;
    if (tid == 0) s_cnt = 0;
    __syncthreads();

    float4 a0 = rp4[tid];
    float4 a1 = rp4[tid + 256];
    float4 a2 = rp4[tid + 512];
    float4 a3 = rp4[tid + 768];

    float vals[16] = {a0.x,a0.y,a0.z,a0.w, a1.x,a1.y,a1.z,a1.w,
                      a2.x,a2.y,a2.z,a2.w, a3.x,a3.y,a3.z,a3.w};
    #pragma unroll
    for (int t = 0; t < 16; t++) {
        if (vals[t] > THRESH) {
            int p = atomicAdd(&s_cnt, 1);
            if (p < SEGCAP) {
                s_u[p] = fkey(vals[t]);
                s_i[p] = base + (t >> 2) * 1024 + tid * 4 + (t & 3);
            }
        }
    }
    __syncthreads();
    const int c  = s_cnt;
    const int cc = min(c, SEGCAP);
    const size_t off = (size_t)(row * SBn + seg) * SEGCAP;
    if (tid < cc) {
        g_su[off + tid] = s_u[tid];
        g_si[off + tid] = s_i[tid];
    }
    if (tid == 0) g_scnt[row * SBn + seg] = c;
}

// ============================================================
// Kernel 2: per-row exact top-200 rank-select over survivors
// (value desc, index-asc ties) + cluster expansion + stable
// pad-compaction. One block (1024 thr) per row.
// Fast identity path when the row has no padding entries.
// Fallback (block-uniform trigger): exact 4x8-bit radix re-scan.
// ============================================================
__global__ void __launch_bounds__(1024) select_expand_kernel(const float* __restrict__ logits,
                                                             const int* __restrict__ clusters,
                                                             float* __restrict__ out) {
    const int row = blockIdx.x;
    const int tid = threadIdx.x;
    const int lane = tid & 31;
    const int wid  = tid >> 5;
    const float*  rp  = logits + (size_t)row * Cn;
    const float4* rp4 = (const float4*)rp;

    __shared__ unsigned s_bu[ROWCAP];      // 8 KB
    __shared__ int      s_bi[ROWCAP];      // 8 KB
    __shared__ int      s_segcnt[SBn];
    __shared__ int      s_segoff[SBn + 1];
    __shared__ int      s_tidx[Kn];
    __shared__ unsigned s_tku[Kn];
    __shared__ float    s_tsc[Kn];
    __shared__ int      s_wsum[32];
    __shared__ int      s_total;
    __shared__ unsigned s_red[256];
    __shared__ unsigned s_prefix;
    __shared__ int      s_kneed;
    __shared__ int      s_cnt;
    __shared__ int      s_bad;

    if (tid < SBn) s_segcnt[tid] = g_scnt[row * SBn + tid];
    __syncthreads();
    if (tid == 0) {
        int acc = 0, bad = 0;
        #pragma unroll
        for (int s = 0; s < SBn; s++) {
            s_segoff[s] = acc;
            int c = s_segcnt[s];
            if (c > SEGCAP) bad = 1;
            acc += min(c, SEGCAP);
        }
        s_segoff[SBn] = acc;
        if (acc < Kn || acc > ROWCAP) bad = 1;
        s_bad = bad;
    }
    __syncthreads();

    int m;
    if (!s_bad) {
        m = s_segoff[SBn];
        // coalesced gather: 64 threads per segment
        {
            const int s  = tid >> 6;            // 0..15
            const int lt = tid & 63;
            const int cnt = s_segoff[s + 1] - s_segoff[s];
            const size_t off = (size_t)(row * SBn + s) * SEGCAP;
            for (int i = lt; i < cnt; i += 64) {
                s_bu[s_segoff[s] + i] = g_su[off + i];
                s_bi[s_segoff[s] + i] = g_si[off + i];
            }
        }
        __syncthreads();
    } else {
        // ---- fallback: exact radix select of the Kn-th largest key ----
        if (tid == 0) { s_prefix = 0u; s_kneed = Kn; s_cnt = 0; }
        __syncthreads();
        for (int shift = 24; shift >= 0; shift -= 8) {
            if (tid < 256) s_red[tid] = 0u;
            __syncthreads();
            const unsigned pref = s_prefix;
            const unsigned mhi  = (shift == 24) ? 0u : (0xFFFFFFFFu << (shift + 8));
            for (int i = tid; i < Cn / 4; i += 1024) {
                float4 v = rp4[i];
                float vals[4] = {v.x, v.y, v.z, v.w};
                #pragma unroll
                for (int t = 0; t < 4; t++) {
                    unsigned u = fkey(vals[t]);
                    if ((u & mhi) == pref) atomicAdd(&s_red[(u >> shift) & 255], 1u);
                }
            }
            __syncthreads();
            if (tid == 0) {
                int kneed = s_kneed;
                int cum = 0;
                int b = 255;
                for (; b > 0; b--) {
                    int c = (int)s_red[b];
                    if (cum + c >= kneed) break;
                    cum += c;
                }
                s_kneed  = kneed - cum;
                s_prefix = pref | ((unsigned)b << shift);
            }
            __syncthreads();
        }
        const unsigned T = s_prefix;
        for (int i = tid; i < Cn / 4; i += 1024) {
            float4 v = rp4[i];
            float vals[4] = {v.x, v.y, v.z, v.w};
            #pragma unroll
            for (int t = 0; t < 4; t++) {
                unsigned u = fkey(vals[t]);
                if (u >= T) {
                    int p = atomicAdd(&s_cnt, 1);
                    if (p < ROWCAP) { s_bu[p] = u; s_bi[p] = i * 4 + t; }
                }
            }
        }
        __syncthreads();
        m = min(s_cnt, ROWCAP);
    }

    // ---- warp-cooperative exact rank-select, 4x-unrolled inner ----
    // rank(i) = #{j : u_j > u_i or (u_j == u_i and idx_j < idx_i)}
    for (int i = wid; i < m; i += 32) {
        const unsigned ui = s_bu[i];
        const int xi = s_bi[i];
        int r = 0;
        int j = lane;
        for (; j + 96 < m; j += 128) {
            unsigned u0 = s_bu[j], u1 = s_bu[j + 32], u2 = s_bu[j + 64], u3 = s_bu[j + 96];
            int b0 = s_bi[j], b1 = s_bi[j + 32], b2 = s_bi[j + 64], b3 = s_bi[j + 96];
            r += (u0 > ui || (u0 == ui && b0 < xi));
            r += (u1 > ui || (u1 == ui && b1 < xi));
            r += (u2 > ui || (u2 == ui && b2 < xi));
            r += (u3 > ui || (u3 == ui && b3 < xi));
        }
        for (; j < m; j += 32) {
            unsigned uj = s_bu[j];
            r += (uj > ui || (uj == ui && s_bi[j] < xi));
        }
        #pragma unroll
        for (int off = 16; off; off >>= 1)
            r += __shfl_xor_sync(0xffffffffu, r, off);
        if (lane == 0 && r < Kn) {
            s_tidx[r] = xi;
            s_tku[r]  = ui;
        }
    }
    __syncthreads();

    // parallel sigmoid over the 200 winners (key-inverse, no gmem read)
    if (tid < Kn) {
        float v = unfkey(s_tku[tid]);
        s_tsc[tid] = __fdividef(1.f, 1.f + __expf(-v));
    }
    __syncthreads();

    // ---- expand clusters ----
    int cand[4];
    float sc = 0.f;
    const int base = tid * 4;
    int haspad = 0;
    if (base < KMn) {
        const int j = base >> 4;                 // 4 | 16 => same topk slot for all 4
        const int idx = min(max(s_tidx[j], 0), Cn - 1);
        sc = s_tsc[j];
        const int4 cc = *(const int4*)(clusters + (size_t)idx * Mn + (base & 15));
        cand[0] = cc.x; cand[1] = cc.y; cand[2] = cc.z; cand[3] = cc.w;
        haspad = (cc.x == NUMLAB) | (cc.y == NUMLAB) | (cc.z == NUMLAB) | (cc.w == NUMLAB);
    }

    if (!__syncthreads_or(haspad)) {
        // ---- FAST PATH: no pads -> identity placement, vector stores ----
        if (base < KMn) {
            int4  ci = make_int4(cand[0], cand[1], cand[2], cand[3]);
            float4 cs = make_float4(sc, sc, sc, sc);
            float4 cf = make_float4((float)cand[0], (float)cand[1],
                                    (float)cand[2], (float)cand[3]);
            *(int4*)  (g_cands   + row * KMn + base) = ci;
            *(float4*)(g_cscores + row * KMn + base) = cs;
            *(float4*)(out + (size_t)row * KMn + base) = cf;
        }
        return;
    }

    // ---- SLOW PATH: stable pad-compaction via block scan ----
    int valid[4];
    int nv = 0;
    if (base < KMn) {
        #pragma unroll
        for (int t = 0; t < 4; t++) {
            valid[t] = (cand[t] != NUMLAB);
            nv += valid[t];
        }
    }
    int x = nv;
    #pragma unroll
    for (int off = 1; off < 32; off <<= 1) {
        int y = __shfl_up_sync(0xffffffffu, x, off);
        if (lane >= off) x += y;
    }
    if (lane == 31) s_wsum[wid] = x;
    __syncthreads();
    if (tid < 32) {
        int v = s_wsum[tid];
        int inc = v;
        #pragma unroll
        for (int off = 1; off < 32; off <<= 1) {
            int y = __shfl_up_sync(0xffffffffu, inc, off);
            if (tid >= off) inc += y;
        }
        s_wsum[tid] = inc - v;
        if (tid == 31) s_total = inc;
    }
    __syncthreads();
    const int total = s_total;
    int vb = s_wsum[wid] + x - nv;

    if (base < KMn) {
        #pragma unroll
        for (int t = 0; t < 4; t++) {
            int pos;
            if (valid[t]) { pos = vb; vb++; }
            else          { pos = total + (base + t) - vb; }
            g_cands[row * KMn + pos]   = cand[t];
            g_cscores[row * KMn + pos] = valid[t] ? sc : 0.f;
            out[(size_t)row * KMn + pos] = (float)cand[t];
        }
    }
}

// ============================================================
// Kernel 3: gather embeddings + dot with h_c, sigmoid, outputs.
// R11 shape (warp per candidate, serial candidates) — best
// measured. Only change: min-8-blocks launch bounds to raise
// occupancy 48 -> 64 warps/SM (more gathers in flight).
// ============================================================
__global__ void __launch_bounds__(256, 8) score_kernel(const float* __restrict__ h_c,
                                                       const float* __restrict__ table,
                                                       float* __restrict__ out) {
    const int row = blockIdx.y;
    __shared__ float sh[Hn];
    for (int i = threadIdx.x; i < Hn; i += 256) sh[i] = h_c[(size_t)row * Hn + i];
    __syncthreads();

    const int warp = threadIdx.x >> 5;
    const int lane = threadIdx.x & 31;
    const int c0 = blockIdx.x * 32 + warp * 4;
    const float4* hv = (const float4*)sh;

    for (int t = 0; t < 4; t++) {
        const int c = c0 + t;
        int label = g_cands[row * KMn + c];
        label = min(max(label, 0), NUMLAB);
        const float4* er = (const float4*)(table + (size_t)label * Hn);
        float acc = 0.f;
        #pragma unroll
        for (int i = 0; i < 4; i++) {
            float4 e = er[lane + i * 32];
            float4 h = hv[lane + i * 32];
            acc += e.x * h.x;
            acc += e.y * h.y;
            acc += e.z * h.z;
            acc += e.w * h.w;
        }
        #pragma unroll
        for (int off = 16; off; off >>= 1)
            acc += __shfl_xor_sync(0xffffffffu, acc, off);
        if (lane == 0) {
            float s = (acc == 0.f) ? 0.f : (1.f / (1.f + __expf(-acc)));
            out[(size_t)Bn * KMn     + (size_t)row * KMn + c] = s;
            out[(size_t)Bn * KMn * 2 + (size_t)row * KMn + c] = s * g_cscores[row * KMn + c];
        }
    }
}

extern "C" void kernel_launch(void* const* d_in, const int* in_sizes, int n_in,
                              void* d_out, int out_size) {
    // Bind inputs by element count (robust to metadata ordering):
    //   meta_logits  128*65536   = 8388608   f32
    //   h_c          128*512     = 65536     f32
    //   embed_table  670001*512  = 343040512 f32
    //   label_clusters 65536*16  = 1048576   i32 (jax x64 disabled -> int32)
    const float* meta = nullptr;
    const float* hc = nullptr;
    const float* table = nullptr;
    const int* clusters = nullptr;
    for (int i = 0; i < n_in; i++) {
        switch (in_sizes[i]) {
            case 8388608:   meta     = (const float*)d_in[i]; break;
            case 65536:     hc       = (const float*)d_in[i]; break;
            case 343040512: table    = (const float*)d_in[i]; break;
            case 1048576:   clusters = (const int*)d_in[i];   break;
            default: break;
        }
    }
    float* out = (float*)d_out; // 3 * 128 * 3200 f32: [cands | cand_scores | product]

    dim3 g1(SBn, Bn);
    collect_kernel<<<g1, 256>>>(meta);
    select_expand_kernel<<<Bn, 1024>>>(meta, clusters, out);
    dim3 g3(KMn / 32, Bn);
    score_kernel<<<g3, 256>>>(hc, table, out);
}

// round 14
// speedup vs baseline: 1.0448x; 1.0261x over previous
#include <cuda_runtime.h>

#define NUMLAB 670000
#define Bn 128
#define Cn 65536
#define Mn 16
#define Hn 512
#define Kn 200
#define KMn 3200        // Kn*Mn
#define SBn 16          // scan segments per row
#define SEGCAP 256      // survivor capacity per segment (expected ~18)
#define ROWCAP 2048     // survivor capacity per row
#define THRESH 2.62f    // raw-logit collect threshold (~288 survivors/row)

// ---- scratch (no allocations allowed) ----
__device__ int      g_scnt[Bn * SBn];
__device__ unsigned g_su[Bn * SBn * SEGCAP];
__device__ int      g_si[Bn * SBn * SEGCAP];
__device__ int      g_cands[Bn * KMn];
__device__ float    g_cscores[Bn * KMn];

// monotone float->uint key: descending float == descending key
__device__ __forceinline__ unsigned fkey(float x) {
    unsigned u = __float_as_uint(x);
    return (u & 0x80000000u) ? ~u : (u | 0x80000000u);
}
__device__ __forceinline__ float unfkey(unsigned k) {
    return __uint_as_float((k & 0x80000000u) ? (k ^ 0x80000000u) : ~k);
}

// ============================================================
// Kernel 1: full-chip streaming collect. grid (SBn, Bn), 256thr.
// Survivors staged in smem, dumped coalesced to a private
// per-segment slot. No global atomics.
// ============================================================
__global__ void __launch_bounds__(256) collect_kernel(const float* __restrict__ logits) {
    const int row = blockIdx.y;
    const int seg = blockIdx.x;
    const int n4  = Cn / 4 / SBn;                 // 1024 float4 per block
    const float4* rp4 = (const float4*)(logits + (size_t)row * Cn) + seg * n4;
    const int base = seg * n4 * 4;
    const int tid = threadIdx.x;

    __shared__ unsigned s_u[SEGCAP];
    __shared__ int      s_i[SEGCAP];
    __shared__ int      s_cnt;
    if (tid == 0) s_cnt = 0;
    __syncthreads();

    float4 a0 = rp4[tid];
    float4 a1 = rp4[tid + 256];
    float4 a2 = rp4[tid + 512];
    float4 a3 = rp4[tid + 768];

    float vals[16] = {a0.x,a0.y,a0.z,a0.w, a1.x,a1.y,a1.z,a1.w,
                      a2.x,a2.y,a2.z,a2.w, a3.x,a3.y,a3.z,a3.w};
    #pragma unroll
    for (int t = 0; t < 16; t++) {
        if (vals[t] > THRESH) {
            int p = atomicAdd(&s_cnt, 1);
            if (p < SEGCAP) {
                s_u[p] = fkey(vals[t]);
                s_i[p] = base + (t >> 2) * 1024 + tid * 4 + (t & 3);
            }
        }
    }
    __syncthreads();
    const int c  = s_cnt;
    const int cc = min(c, SEGCAP);
    const size_t off = (size_t)(row * SBn + seg) * SEGCAP;
    if (tid < cc) {
        g_su[off + tid] = s_u[tid];
        g_si[off + tid] = s_i[tid];
    }
    if (tid == 0) g_scnt[row * SBn + seg] = c;
}

// ============================================================
// Kernel 2: per-row exact top-200 rank-select over survivors
// (value desc, index-asc ties) + cluster expansion + stable
// pad-compaction. One block (1024 thr) per row.
// Fast identity path when the row has no padding entries.
// Fallback (block-uniform trigger): exact 4x8-bit radix re-scan.
// ============================================================
__global__ void __launch_bounds__(1024) select_expand_kernel(const float* __restrict__ logits,
                                                             const int* __restrict__ clusters,
                                                             float* __restrict__ out) {
    const int row = blockIdx.x;
    const int tid = threadIdx.x;
    const int lane = tid & 31;
    const int wid  = tid >> 5;
    const float*  rp  = logits + (size_t)row * Cn;
    const float4* rp4 = (const float4*)rp;

    __shared__ unsigned s_bu[ROWCAP];      // 8 KB
    __shared__ int      s_bi[ROWCAP];      // 8 KB
    __shared__ int      s_segcnt[SBn];
    __shared__ int      s_segoff[SBn + 1];
    __shared__ int      s_tidx[Kn];
    __shared__ unsigned s_tku[Kn];
    __shared__ float    s_tsc[Kn];
    __shared__ int      s_wsum[32];
    __shared__ int      s_total;
    __shared__ unsigned s_red[256];
    __shared__ unsigned s_prefix;
    __shared__ int      s_kneed;
    __shared__ int      s_cnt;
    __shared__ int      s_bad;

    if (tid < SBn) s_segcnt[tid] = g_scnt[row * SBn + tid];
    __syncthreads();
    if (tid == 0) {
        int acc = 0, bad = 0;
        #pragma unroll
        for (int s = 0; s < SBn; s++) {
            s_segoff[s] = acc;
            int c = s_segcnt[s];
            if (c > SEGCAP) bad = 1;
            acc += min(c, SEGCAP);
        }
        s_segoff[SBn] = acc;
        if (acc < Kn || acc > ROWCAP) bad = 1;
        s_bad = bad;
    }
    __syncthreads();

    int m;
    if (!s_bad) {
        m = s_segoff[SBn];
        // coalesced gather: 64 threads per segment
        {
            const int s  = tid >> 6;            // 0..15
            const int lt = tid & 63;
            const int cnt = s_segoff[s + 1] - s_segoff[s];
            const size_t off = (size_t)(row * SBn + s) * SEGCAP;
            for (int i = lt; i < cnt; i += 64) {
                s_bu[s_segoff[s] + i] = g_su[off + i];
                s_bi[s_segoff[s] + i] = g_si[off + i];
            }
        }
        __syncthreads();
    } else {
        // ---- fallback: exact radix select of the Kn-th largest key ----
        if (tid == 0) { s_prefix = 0u; s_kneed = Kn; s_cnt = 0; }
        __syncthreads();
        for (int shift = 24; shift >= 0; shift -= 8) {
            if (tid < 256) s_red[tid] = 0u;
            __syncthreads();
            const unsigned pref = s_prefix;
            const unsigned mhi  = (shift == 24) ? 0u : (0xFFFFFFFFu << (shift + 8));
            for (int i = tid; i < Cn / 4; i += 1024) {
                float4 v = rp4[i];
                float vals[4] = {v.x, v.y, v.z, v.w};
                #pragma unroll
                for (int t = 0; t < 4; t++) {
                    unsigned u = fkey(vals[t]);
                    if ((u & mhi) == pref) atomicAdd(&s_red[(u >> shift) & 255], 1u);
                }
            }
            __syncthreads();
            if (tid == 0) {
                int kneed = s_kneed;
                int cum = 0;
                int b = 255;
                for (; b > 0; b--) {
                    int c = (int)s_red[b];
                    if (cum + c >= kneed) break;
                    cum += c;
                }
                s_kneed  = kneed - cum;
                s_prefix = pref | ((unsigned)b << shift);
            }
            __syncthreads();
        }
        const unsigned T = s_prefix;
        for (int i = tid; i < Cn / 4; i += 1024) {
            float4 v = rp4[i];
            float vals[4] = {v.x, v.y, v.z, v.w};
            #pragma unroll
            for (int t = 0; t < 4; t++) {
                unsigned u = fkey(vals[t]);
                if (u >= T) {
                    int p = atomicAdd(&s_cnt, 1);
                    if (p < ROWCAP) { s_bu[p] = u; s_bi[p] = i * 4 + t; }
                }
            }
        }
        __syncthreads();
        m = min(s_cnt, ROWCAP);
    }

    // ---- warp-cooperative exact rank-select, 4x-unrolled inner ----
    // rank(i) = #{j : u_j > u_i or (u_j == u_i and idx_j < idx_i)}
    for (int i = wid; i < m; i += 32) {
        const unsigned ui = s_bu[i];
        const int xi = s_bi[i];
        int r = 0;
        int j = lane;
        for (; j + 96 < m; j += 128) {
            unsigned u0 = s_bu[j], u1 = s_bu[j + 32], u2 = s_bu[j + 64], u3 = s_bu[j + 96];
            int b0 = s_bi[j], b1 = s_bi[j + 32], b2 = s_bi[j + 64], b3 = s_bi[j + 96];
            r += (u0 > ui || (u0 == ui && b0 < xi));
            r += (u1 > ui || (u1 == ui && b1 < xi));
            r += (u2 > ui || (u2 == ui && b2 < xi));
            r += (u3 > ui || (u3 == ui && b3 < xi));
        }
        for (; j < m; j += 32) {
            unsigned uj = s_bu[j];
            r += (uj > ui || (uj == ui && s_bi[j] < xi));
        }
        #pragma unroll
        for (int off = 16; off; off >>= 1)
            r += __shfl_xor_sync(0xffffffffu, r, off);
        if (lane == 0 && r < Kn) {
            s_tidx[r] = xi;
            s_tku[r]  = ui;
        }
    }
    __syncthreads();

    // parallel sigmoid over the 200 winners (key-inverse, no gmem read)
    if (tid < Kn) {
        float v = unfkey(s_tku[tid]);
        s_tsc[tid] = __fdividef(1.f, 1.f + __expf(-v));
    }
    __syncthreads();

    // ---- expand clusters ----
    int cand[4];
    float sc = 0.f;
    const int base = tid * 4;
    int haspad = 0;
    if (base < KMn) {
        const int j = base >> 4;                 // 4 | 16 => same topk slot for all 4
        const int idx = min(max(s_tidx[j], 0), Cn - 1);
        sc = s_tsc[j];
        const int4 cc = *(const int4*)(clusters + (size_t)idx * Mn + (base & 15));
        cand[0] = cc.x; cand[1] = cc.y; cand[2] = cc.z; cand[3] = cc.w;
        haspad = (cc.x == NUMLAB) | (cc.y == NUMLAB) | (cc.z == NUMLAB) | (cc.w == NUMLAB);
    }

    if (!__syncthreads_or(haspad)) {
        // ---- FAST PATH: no pads -> identity placement, vector stores ----
        if (base < KMn) {
            int4  ci = make_int4(cand[0], cand[1], cand[2], cand[3]);
            float4 cs = make_float4(sc, sc, sc, sc);
            float4 cf = make_float4((float)cand[0], (float)cand[1],
                                    (float)cand[2], (float)cand[3]);
            *(int4*)  (g_cands   + row * KMn + base) = ci;
            *(float4*)(g_cscores + row * KMn + base) = cs;
            *(float4*)(out + (size_t)row * KMn + base) = cf;
        }
        return;
    }

    // ---- SLOW PATH: stable pad-compaction via block scan ----
    int valid[4];
    int nv = 0;
    if (base < KMn) {
        #pragma unroll
        for (int t = 0; t < 4; t++) {
            valid[t] = (cand[t] != NUMLAB);
            nv += valid[t];
        }
    }
    int x = nv;
    #pragma unroll
    for (int off = 1; off < 32; off <<= 1) {
        int y = __shfl_up_sync(0xffffffffu, x, off);
        if (lane >= off) x += y;
    }
    if (lane == 31) s_wsum[wid] = x;
    __syncthreads();
    if (tid < 32) {
        int v = s_wsum[tid];
        int inc = v;
        #pragma unroll
        for (int off = 1; off < 32; off <<= 1) {
            int y = __shfl_up_sync(0xffffffffu, inc, off);
            if (tid >= off) inc += y;
        }
        s_wsum[tid] = inc - v;
        if (tid == 31) s_total = inc;
    }
    __syncthreads();
    const int total = s_total;
    int vb = s_wsum[wid] + x - nv;

    if (base < KMn) {
        #pragma unroll
        for (int t = 0; t < 4; t++) {
            int pos;
            if (valid[t]) { pos = vb; vb++; }
            else          { pos = total + (base + t) - vb; }
            g_cands[row * KMn + pos]   = cand[t];
            g_cscores[row * KMn + pos] = valid[t] ? sc : 0.f;
            out[(size_t)row * KMn + pos] = (float)cand[t];
        }
    }
}

// ============================================================
// Kernel 3: gather embeddings + dot with h_c, sigmoid, outputs.
// R11 shape (warp per candidate, serial candidate loop — best
// measured). Single change vs R11: the 4 label loads are
// hoisted and issued as independent loads up front, removing
// serial label-load latency between candidates. Per-candidate
// accumulation order unchanged.
// ============================================================
__global__ void __launch_bounds__(256) score_kernel(const float* __restrict__ h_c,
                                                    const float* __restrict__ table,
                                                    float* __restrict__ out) {
    const int row = blockIdx.y;
    __shared__ float sh[Hn];
    for (int i = threadIdx.x; i < Hn; i += 256) sh[i] = h_c[(size_t)row * Hn + i];
    __syncthreads();

    const int warp = threadIdx.x >> 5;
    const int lane = threadIdx.x & 31;
    const int c0 = blockIdx.x * 32 + warp * 4;
    const float4* hv = (const float4*)sh;

    // prefetch the 4 labels (independent loads)
    int lab[4];
    #pragma unroll
    for (int t = 0; t < 4; t++) {
        int l = g_cands[row * KMn + c0 + t];
        lab[t] = min(max(l, 0), NUMLAB);
    }

    for (int t = 0; t < 4; t++) {
        const int c = c0 + t;
        const float4* er = (const float4*)(table + (size_t)lab[t] * Hn);
        float acc = 0.f;
        #pragma unroll
        for (int i = 0; i < 4; i++) {
            float4 e = er[lane + i * 32];
            float4 h = hv[lane + i * 32];
            acc += e.x * h.x;
            acc += e.y * h.y;
            acc += e.z * h.z;
            acc += e.w * h.w;
        }
        #pragma unroll
        for (int off = 16; off; off >>= 1)
            acc += __shfl_xor_sync(0xffffffffu, acc, off);
        if (lane == 0) {
            float s = (acc == 0.f) ? 0.f : (1.f / (1.f + __expf(-acc)));
            out[(size_t)Bn * KMn     + (size_t)row * KMn + c] = s;
            out[(size_t)Bn * KMn * 2 + (size_t)row * KMn + c] = s * g_cscores[row * KMn + c];
        }
    }
}

extern "C" void kernel_launch(void* const* d_in, const int* in_sizes, int n_in,
                              void* d_out, int out_size) {
    // Bind inputs by element count (robust to metadata ordering):
    //   meta_logits  128*65536   = 8388608   f32
    //   h_c          128*512     = 65536     f32
    //   embed_table  670001*512  = 343040512 f32
    //   label_clusters 65536*16  = 1048576   i32 (jax x64 disabled -> int32)
    const float* meta = nullptr;
    const float* hc = nullptr;
    const float* table = nullptr;
    const int* clusters = nullptr;
    for (int i = 0; i < n_in; i++) {
        switch (in_sizes[i]) {
            case 8388608:   meta     = (const float*)d_in[i]; break;
            case 65536:     hc       = (const float*)d_in[i]; break;
            case 343040512: table    = (const float*)d_in[i]; break;
            case 1048576:   clusters = (const int*)d_in[i];   break;
            default: break;
        }
    }
    float* out = (float*)d_out; // 3 * 128 * 3200 f32: [cands | cand_scores | product]

    dim3 g1(SBn, Bn);
    collect_kernel<<<g1, 256>>>(meta);
    select_expand_kernel<<<Bn, 1024>>>(meta, clusters, out);
    dim3 g3(KMn / 32, Bn);
    score_kernel<<<g3, 256>>>(hc, table, out);
}

// round 15
// speedup vs baseline: 1.1060x; 1.0586x over previous
#include <cuda_runtime.h>

#define NUMLAB 670000
#define Bn 128
#define Cn 65536
#define Mn 16
#define Hn 512
#define Kn 200
#define KMn 3200        // Kn*Mn
#define SBn 16          // scan segments per row
#define SEGCAP 256      // survivor capacity per segment (expected ~18)
#define ROWCAP 2048     // survivor capacity per row
#define THRESH 2.62f    // raw-logit collect threshold (~288 survivors/row)

// ---- scratch (no allocations allowed) ----
__device__ int      g_scnt[Bn * SBn];
__device__ unsigned g_su[Bn * SBn * SEGCAP];
__device__ int      g_si[Bn * SBn * SEGCAP];
__device__ int      g_cands[Bn * KMn];
__device__ float    g_cscores[Bn * KMn];

// monotone float->uint key: descending float == descending key
__device__ __forceinline__ unsigned fkey(float x) {
    unsigned u = __float_as_uint(x);
    return (u & 0x80000000u) ? ~u : (u | 0x80000000u);
}
__device__ __forceinline__ float unfkey(unsigned k) {
    return __uint_as_float((k & 0x80000000u) ? (k ^ 0x80000000u) : ~k);
}

// ============================================================
// Kernel 1: full-chip streaming collect. grid (SBn, Bn), 256thr.
// Survivors staged in smem, dumped coalesced to a private
// per-segment slot. No global atomics. (R11 body, unchanged.)
// ============================================================
__global__ void __launch_bounds__(256) collect_kernel(const float* __restrict__ logits) {
    const int row = blockIdx.y;
    const int seg = blockIdx.x;
    const int n4  = Cn / 4 / SBn;                 // 1024 float4 per block
    const float4* rp4 = (const float4*)(logits + (size_t)row * Cn) + seg * n4;
    const int base = seg * n4 * 4;
    const int tid = threadIdx.x;

    __shared__ unsigned s_u[SEGCAP];
    __shared__ int      s_i[SEGCAP];
    __shared__ int      s_cnt;
    if (tid == 0) s_cnt = 0;
    __syncthreads();

    float4 a0 = rp4[tid];
    float4 a1 = rp4[tid + 256];
    float4 a2 = rp4[tid + 512];
    float4 a3 = rp4[tid + 768];

    float vals[16] = {a0.x,a0.y,a0.z,a0.w, a1.x,a1.y,a1.z,a1.w,
                      a2.x,a2.y,a2.z,a2.w, a3.x,a3.y,a3.z,a3.w};
    #pragma unroll
    for (int t = 0; t < 16; t++) {
        if (vals[t] > THRESH) {
            int p = atomicAdd(&s_cnt, 1);
            if (p < SEGCAP) {
                s_u[p] = fkey(vals[t]);
                s_i[p] = base + (t >> 2) * 1024 + tid * 4 + (t & 3);
            }
        }
    }
    __syncthreads();
    const int c  = s_cnt;
    const int cc = min(c, SEGCAP);
    const size_t off = (size_t)(row * SBn + seg) * SEGCAP;
    if (tid < cc) {
        g_su[off + tid] = s_u[tid];
        g_si[off + tid] = s_i[tid];
    }
    if (tid == 0) g_scnt[row * SBn + seg] = c;
}

// ============================================================
// Kernel 2: per-row exact top-200 rank-select over survivors
// (value desc, index-asc ties) + cluster expansion + stable
// pad-compaction. One block (1024 thr) per row. (R11 body;
// only addition: PDL grid-dependency sync before first read.)
// ============================================================
__global__ void __launch_bounds__(1024) select_expand_kernel(const float* __restrict__ logits,
                                                             const int* __restrict__ clusters,
                                                             float* __restrict__ out) {
    const int row = blockIdx.x;
    const int tid = threadIdx.x;
    const int lane = tid & 31;
    const int wid  = tid >> 5;
    const float*  rp  = logits + (size_t)row * Cn;
    const float4* rp4 = (const float4*)rp;

    __shared__ unsigned s_bu[ROWCAP];      // 8 KB
    __shared__ int      s_bi[ROWCAP];      // 8 KB
    __shared__ int      s_segcnt[SBn];
    __shared__ int      s_segoff[SBn + 1];
    __shared__ int      s_tidx[Kn];
    __shared__ unsigned s_tku[Kn];
    __shared__ float    s_tsc[Kn];
    __shared__ int      s_wsum[32];
    __shared__ int      s_total;
    __shared__ unsigned s_red[256];
    __shared__ unsigned s_prefix;
    __shared__ int      s_kneed;
    __shared__ int      s_cnt;
    __shared__ int      s_bad;

    // PDL: wait for collect_kernel's results before consuming them.
    cudaGridDependencySynchronize();

    if (tid < SBn) s_segcnt[tid] = g_scnt[row * SBn + tid];
    __syncthreads();
    if (tid == 0) {
        int acc = 0, bad = 0;
        #pragma unroll
        for (int s = 0; s < SBn; s++) {
            s_segoff[s] = acc;
            int c = s_segcnt[s];
            if (c > SEGCAP) bad = 1;
            acc += min(c, SEGCAP);
        }
        s_segoff[SBn] = acc;
        if (acc < Kn || acc > ROWCAP) bad = 1;
        s_bad = bad;
    }
    __syncthreads();

    int m;
    if (!s_bad) {
        m = s_segoff[SBn];
        // coalesced gather: 64 threads per segment
        {
            const int s  = tid >> 6;            // 0..15
            const int lt = tid & 63;
            const int cnt = s_segoff[s + 1] - s_segoff[s];
            const size_t off = (size_t)(row * SBn + s) * SEGCAP;
            for (int i = lt; i < cnt; i += 64) {
                s_bu[s_segoff[s] + i] = g_su[off + i];
                s_bi[s_segoff[s] + i] = g_si[off + i];
            }
        }
        __syncthreads();
    } else {
        // ---- fallback: exact radix select of the Kn-th largest key ----
        if (tid == 0) { s_prefix = 0u; s_kneed = Kn; s_cnt = 0; }
        __syncthreads();
        for (int shift = 24; shift >= 0; shift -= 8) {
            if (tid < 256) s_red[tid] = 0u;
            __syncthreads();
            const unsigned pref = s_prefix;
            const unsigned mhi  = (shift == 24) ? 0u : (0xFFFFFFFFu << (shift + 8));
            for (int i = tid; i < Cn / 4; i += 1024) {
                float4 v = rp4[i];
                float vals[4] = {v.x, v.y, v.z, v.w};
                #pragma unroll
                for (int t = 0; t < 4; t++) {
                    unsigned u = fkey(vals[t]);
                    if ((u & mhi) == pref) atomicAdd(&s_red[(u >> shift) & 255], 1u);
                }
            }
            __syncthreads();
            if (tid == 0) {
                int kneed = s_kneed;
                int cum = 0;
                int b = 255;
                for (; b > 0; b--) {
                    int c = (int)s_red[b];
                    if (cum + c >= kneed) break;
                    cum += c;
                }
                s_kneed  = kneed - cum;
                s_prefix = pref | ((unsigned)b << shift);
            }
            __syncthreads();
        }
        const unsigned T = s_prefix;
        for (int i = tid; i < Cn / 4; i += 1024) {
            float4 v = rp4[i];
            float vals[4] = {v.x, v.y, v.z, v.w};
            #pragma unroll
            for (int t = 0; t < 4; t++) {
                unsigned u = fkey(vals[t]);
                if (u >= T) {
                    int p = atomicAdd(&s_cnt, 1);
                    if (p < ROWCAP) { s_bu[p] = u; s_bi[p] = i * 4 + t; }
                }
            }
        }
        __syncthreads();
        m = min(s_cnt, ROWCAP);
    }

    // ---- warp-cooperative exact rank-select, 4x-unrolled inner ----
    // rank(i) = #{j : u_j > u_i or (u_j == u_i and idx_j < idx_i)}
    for (int i = wid; i < m; i += 32) {
        const unsigned ui = s_bu[i];
        const int xi = s_bi[i];
        int r = 0;
        int j = lane;
        for (; j + 96 < m; j += 128) {
            unsigned u0 = s_bu[j], u1 = s_bu[j + 32], u2 = s_bu[j + 64], u3 = s_bu[j + 96];
            int b0 = s_bi[j], b1 = s_bi[j + 32], b2 = s_bi[j + 64], b3 = s_bi[j + 96];
            r += (u0 > ui || (u0 == ui && b0 < xi));
            r += (u1 > ui || (u1 == ui && b1 < xi));
            r += (u2 > ui || (u2 == ui && b2 < xi));
            r += (u3 > ui || (u3 == ui && b3 < xi));
        }
        for (; j < m; j += 32) {
            unsigned uj = s_bu[j];
            r += (uj > ui || (uj == ui && s_bi[j] < xi));
        }
        #pragma unroll
        for (int off = 16; off; off >>= 1)
            r += __shfl_xor_sync(0xffffffffu, r, off);
        if (lane == 0 && r < Kn) {
            s_tidx[r] = xi;
            s_tku[r]  = ui;
        }
    }
    __syncthreads();

    // parallel sigmoid over the 200 winners (key-inverse, no gmem read)
    if (tid < Kn) {
        float v = unfkey(s_tku[tid]);
        s_tsc[tid] = __fdividef(1.f, 1.f + __expf(-v));
    }
    __syncthreads();

    // ---- expand clusters ----
    int cand[4];
    float sc = 0.f;
    const int base = tid * 4;
    int haspad = 0;
    if (base < KMn) {
        const int j = base >> 4;                 // 4 | 16 => same topk slot for all 4
        const int idx = min(max(s_tidx[j], 0), Cn - 1);
        sc = s_tsc[j];
        const int4 cc = *(const int4*)(clusters + (size_t)idx * Mn + (base & 15));
        cand[0] = cc.x; cand[1] = cc.y; cand[2] = cc.z; cand[3] = cc.w;
        haspad = (cc.x == NUMLAB) | (cc.y == NUMLAB) | (cc.z == NUMLAB) | (cc.w == NUMLAB);
    }

    if (!__syncthreads_or(haspad)) {
        // ---- FAST PATH: no pads -> identity placement, vector stores ----
        if (base < KMn) {
            int4  ci = make_int4(cand[0], cand[1], cand[2], cand[3]);
            float4 cs = make_float4(sc, sc, sc, sc);
            float4 cf = make_float4((float)cand[0], (float)cand[1],
                                    (float)cand[2], (float)cand[3]);
            *(int4*)  (g_cands   + row * KMn + base) = ci;
            *(float4*)(g_cscores + row * KMn + base) = cs;
            *(float4*)(out + (size_t)row * KMn + base) = cf;
        }
        return;
    }

    // ---- SLOW PATH: stable pad-compaction via block scan ----
    int valid[4];
    int nv = 0;
    if (base < KMn) {
        #pragma unroll
        for (int t = 0; t < 4; t++) {
            valid[t] = (cand[t] != NUMLAB);
            nv += valid[t];
        }
    }
    int x = nv;
    #pragma unroll
    for (int off = 1; off < 32; off <<= 1) {
        int y = __shfl_up_sync(0xffffffffu, x, off);
        if (lane >= off) x += y;
    }
    if (lane == 31) s_wsum[wid] = x;
    __syncthreads();
    if (tid < 32) {
        int v = s_wsum[tid];
        int inc = v;
        #pragma unroll
        for (int off = 1; off < 32; off <<= 1) {
            int y = __shfl_up_sync(0xffffffffu, inc, off);
            if (tid >= off) inc += y;
        }
        s_wsum[tid] = inc - v;
        if (tid == 31) s_total = inc;
    }
    __syncthreads();
    const int total = s_total;
    int vb = s_wsum[wid] + x - nv;

    if (base < KMn) {
        #pragma unroll
        for (int t = 0; t < 4; t++) {
            int pos;
            if (valid[t]) { pos = vb; vb++; }
            else          { pos = total + (base + t) - vb; }
            g_cands[row * KMn + pos]   = cand[t];
            g_cscores[row * KMn + pos] = valid[t] ? sc : 0.f;
            out[(size_t)row * KMn + pos] = (float)cand[t];
        }
    }
}

// ============================================================
// Kernel 3: gather embeddings + dot with h_c, sigmoid, outputs.
// EXACT R11 body (best measured: 119.6us @ 80% HBM). Only
// addition: h_c smem preload overlaps the producer kernel via
// PDL; grid-dependency sync before the first g_cands read.
// ============================================================
__global__ void __launch_bounds__(256) score_kernel(const float* __restrict__ h_c,
                                                    const float* __restrict__ table,
                                                    float* __restrict__ out) {
    const int row = blockIdx.y;
    __shared__ float sh[Hn];
    for (int i = threadIdx.x; i < Hn; i += 256) sh[i] = h_c[(size_t)row * Hn + i];

    // PDL: h_c preload above overlaps select_expand's tail.
    cudaGridDependencySynchronize();
    __syncthreads();

    const int warp = threadIdx.x >> 5;
    const int lane = threadIdx.x & 31;
    const int c0 = blockIdx.x * 32 + warp * 4;
    const float4* hv = (const float4*)sh;

    for (int t = 0; t < 4; t++) {
        const int c = c0 + t;
        int label = g_cands[row * KMn + c];
        label = min(max(label, 0), NUMLAB);
        const float4* er = (const float4*)(table + (size_t)label * Hn);
        float acc = 0.f;
        #pragma unroll
        for (int i = 0; i < 4; i++) {
            float4 e = er[lane + i * 32];
            float4 h = hv[lane + i * 32];
            acc += e.x * h.x;
            acc += e.y * h.y;
            acc += e.z * h.z;
            acc += e.w * h.w;
        }
        #pragma unroll
        for (int off = 16; off; off >>= 1)
            acc += __shfl_xor_sync(0xffffffffu, acc, off);
        if (lane == 0) {
            float s = (acc == 0.f) ? 0.f : (1.f / (1.f + __expf(-acc)));
            out[(size_t)Bn * KMn     + (size_t)row * KMn + c] = s;
            out[(size_t)Bn * KMn * 2 + (size_t)row * KMn + c] = s * g_cscores[row * KMn + c];
        }
    }
}

extern "C" void kernel_launch(void* const* d_in, const int* in_sizes, int n_in,
                              void* d_out, int out_size) {
    // Bind inputs by element count (robust to metadata ordering):
    //   meta_logits  128*65536   = 8388608   f32
    //   h_c          128*512     = 65536     f32
    //   embed_table  670001*512  = 343040512 f32
    //   label_clusters 65536*16  = 1048576   i32 (jax x64 disabled -> int32)
    const float* meta = nullptr;
    const float* hc = nullptr;
    const float* table = nullptr;
    const int* clusters = nullptr;
    for (int i = 0; i < n_in; i++) {
        switch (in_sizes[i]) {
            case 8388608:   meta     = (const float*)d_in[i]; break;
            case 65536:     hc       = (const float*)d_in[i]; break;
            case 343040512: table    = (const float*)d_in[i]; break;
            case 1048576:   clusters = (const int*)d_in[i];   break;
            default: break;
        }
    }
    float* out = (float*)d_out; // 3 * 128 * 3200 f32: [cands | cand_scores | product]

    // Kernel 1: normal launch.
    dim3 g1(SBn, Bn);
    collect_kernel<<<g1, 256>>>(meta);

    // Kernels 2 & 3: programmatic dependent launch (PDL) — the secondary
    // grid may launch while the primary drains; data dependency is enforced
    // by cudaGridDependencySynchronize() inside the secondary kernels.
    cudaLaunchAttribute pdl[1];
    pdl[0].id = cudaLaunchAttributeProgrammaticStreamSerialization;
    pdl[0].val.programmaticStreamSerializationAllowed = 1;

    {
        cudaLaunchConfig_t cfg = {};
        cfg.gridDim  = dim3(Bn, 1, 1);
        cfg.blockDim = dim3(1024, 1, 1);
        cfg.attrs    = pdl;
        cfg.numAttrs = 1;
        cudaLaunchKernelEx(&cfg, select_expand_kernel, meta, clusters, (float*)out);
    }
    {
        cudaLaunchConfig_t cfg = {};
        cfg.gridDim  = dim3(KMn / 32, Bn, 1);
        cfg.blockDim = dim3(256, 1, 1);
        cfg.attrs    = pdl;
        cfg.numAttrs = 1;
        cudaLaunchKernelEx(&cfg, score_kernel, hc, table, (float*)out);
    }
}